// round 12
// baseline (speedup 1.0000x reference)
#include <cuda_runtime.h>
#include <math.h>

// rbfLayer, round 12: R10 base + epilogue K via broadcast LDG.128 (L1-resident
// 1KB repacked buffer) instead of smem (LDS.128 costs ~4 smem-cyc regardless of
// broadcast; LDG dedups to 1 wavefront). snbr smem staging dropped (direct
// broadcast LDG of nbr quads). Split epilogue accumulators (2 chains per i).

#define PTS_PER_BLOCK 32
#define BLOCK_THREADS 128
#define SSW_STRIDE 18          // float2 per point row (16 + 2 pad)

typedef unsigned long long u64;

__device__ __align__(128) ulonglong2 g_k[256];   // 1KB repacked kernel

__device__ __forceinline__ u64 pack2(float lo, float hi) {
    u64 r;
    asm("mov.b64 %0, {%1,%2};" : "=l"(r)
        : "r"(__float_as_int(lo)), "r"(__float_as_int(hi)));
    return r;
}
__device__ __forceinline__ void unpack2(u64 v, float& lo, float& hi) {
    int a, b;
    asm("mov.b64 {%0,%1}, %2;" : "=r"(a), "=r"(b) : "l"(v));
    lo = __int_as_float(a); hi = __int_as_float(b);
}
__device__ __forceinline__ u64 fma2(u64 a, u64 b, u64 c) {
    u64 d;
    asm("fma.rn.f32x2 %0, %1, %2, %3;" : "=l"(d) : "l"(a), "l"(b), "l"(c));
    return d;
}
__device__ __forceinline__ u64 mul2(u64 a, u64 b) {
    u64 d;
    asm("mul.rn.f32x2 %0, %1, %2;" : "=l"(d) : "l"(a), "l"(b));
    return d;
}
__device__ __forceinline__ u64 add2(u64 a, u64 b) {
    u64 d;
    asm("add.rn.f32x2 %0, %1, %2;" : "=l"(d) : "l"(a), "l"(b));
    return d;
}

__device__ __forceinline__ void edge_geom(float dx, float dy,
                                          float& sr, float& sa) {
    float d2 = fmaxf(fmaf(dx, dx, dy * dy), 1e-24f);
    float rinv = rsqrtf(d2);
    sr = d2 * rinv * 1.5f;

    float ax = fabsf(dx), ay = fabsf(dy);
    float mn = fminf(ax, ay);
    float mx = fmaxf(fmaxf(ax, ay), 1e-30f);
    float tq = __fdividef(mn, mx);
    float t2 = tq * tq;
    float pl = -0.0117212f;
    pl = fmaf(pl, t2, 0.05265332f);
    pl = fmaf(pl, t2, -0.11643287f);
    pl = fmaf(pl, t2, 0.19354346f);
    pl = fmaf(pl, t2, -0.33262347f);
    pl = fmaf(pl, t2, 0.99997726f);
    float ang = pl * tq;
    if (ay > ax) ang = 1.5707963267948966f - ang;
    if (dx < 0.0f) ang = 3.141592653589793f - ang;
    float th = ang * 0.3183098861837907f;
    th = (dy < 0.0f) ? -th : th;
    sa = fmaf(th, 2.0f, 2.0f);
}

__device__ __forceinline__ void decode_w(float sr, float sa,
                                         float4& WA, float4& WR) {
    int   kr = (int)sr;
    float fr = sr - (float)kr;
    int   ka = (int)sa;
    float fa = sa - (float)ka;
    int   k0 = ka & 3;
    int   k1 = (ka + 1) & 3;

    WA.x = (k0 == 0) ? (1.0f - fa) : ((k1 == 0) ? fa : 0.0f);
    WA.y = (k0 == 1) ? (1.0f - fa) : ((k1 == 1) ? fa : 0.0f);
    WA.z = (k0 == 2) ? (1.0f - fa) : ((k1 == 2) ? fa : 0.0f);
    WA.w = (k0 == 3) ? (1.0f - fa) : ((k1 == 3) ? fa : 0.0f);

    WR.x = (kr == 0) ? (1.0f - fr) : 0.0f;
    WR.y = (kr == 1) ? (1.0f - fr) : ((kr == 0) ? fr : 0.0f);
    WR.z = (kr == 2) ? (1.0f - fr) : ((kr == 1) ? fr : 0.0f);
    WR.w = (kr == 2) ? fr : 0.0f;
}

__device__ __forceinline__ void accum16(const float4& WA, const float4& WR,
                                        u64 fv2, u64 Zp[16]) {
    u64 t0 = mul2(pack2(WA.x, WA.x), fv2);
    u64 t1 = mul2(pack2(WA.y, WA.y), fv2);
    u64 t2 = mul2(pack2(WA.z, WA.z), fv2);
    u64 t3 = mul2(pack2(WA.w, WA.w), fv2);
    u64 r0 = pack2(WR.x, WR.x);
    u64 r1 = pack2(WR.y, WR.y);
    u64 r2 = pack2(WR.z, WR.z);
    u64 r3 = pack2(WR.w, WR.w);

    Zp[0]  = fma2(r0, t0, Zp[0]);   Zp[1]  = fma2(r0, t1, Zp[1]);
    Zp[2]  = fma2(r0, t2, Zp[2]);   Zp[3]  = fma2(r0, t3, Zp[3]);
    Zp[4]  = fma2(r1, t0, Zp[4]);   Zp[5]  = fma2(r1, t1, Zp[5]);
    Zp[6]  = fma2(r1, t2, Zp[6]);   Zp[7]  = fma2(r1, t3, Zp[7]);
    Zp[8]  = fma2(r2, t0, Zp[8]);   Zp[9]  = fma2(r2, t1, Zp[9]);
    Zp[10] = fma2(r2, t2, Zp[10]);  Zp[11] = fma2(r2, t3, Zp[11]);
    Zp[12] = fma2(r3, t0, Zp[12]);  Zp[13] = fma2(r3, t1, Zp[13]);
    Zp[14] = fma2(r3, t2, Zp[14]);  Zp[15] = fma2(r3, t3, Zp[15]);
}

// ---------------- prepass: repack K into g_k (one block) ----------------
__global__ void repack_kernel(const float* __restrict__ kern)
{
    int idx = threadIdx.x;          // 0..255
    if (idx < 256) {
        int tt  = idx & 3;
        int nm2 = (idx >> 2) & 7;
        int i   = idx >> 5;
        int n0 = 2 * nm2, n1 = 2 * nm2 + 1;
        ulonglong2 v;
        v.x = pack2(kern[(i * 8 + 2 * tt)     * 16 + n0],
                    kern[(i * 8 + 2 * tt + 1) * 16 + n0]);
        v.y = pack2(kern[(i * 8 + 2 * tt)     * 16 + n1],
                    kern[(i * 8 + 2 * tt + 1) * 16 + n1]);
        g_k[idx] = v;
    }
}

__global__ __launch_bounds__(BLOCK_THREADS, 8)
void rbf_layer_kernel(const float2* __restrict__ pos,
                      const float*  __restrict__ feat,
                      const int*    __restrict__ nbrs,
                      const int*    __restrict__ rsp,
                      float*        __restrict__ out,
                      int n_pts, int n_edges)
{
    __shared__ float2 ssw[PTS_PER_BLOCK * SSW_STRIDE];  // 4.6 KB (sr,sa)

    int tid = threadIdx.x;
    int p0  = blockIdx.x * PTS_PER_BLOCK;

    // ---- Phase 1: geometry -> smem (uniform-row assumption; phase 2
    //      verifies beg==16*point && cnt==16 before using it) ----
    {
        int ptl = tid >> 2;                 // local point 0..31
        int g   = tid & 3;                  // edge quad 0..3
        int e0  = (p0 + ptl) * 16 + g * 4;
        int4 nbq;
        if (e0 + 3 < n_edges) {
            nbq = __ldg((const int4*)(nbrs + e0));
        } else {
            nbq.x = (e0 + 0 < n_edges) ? __ldg(nbrs + e0 + 0) : 0;
            nbq.y = (e0 + 1 < n_edges) ? __ldg(nbrs + e0 + 1) : 0;
            nbq.z = (e0 + 2 < n_edges) ? __ldg(nbrs + e0 + 2) : 0;
            nbq.w = (e0 + 3 < n_edges) ? __ldg(nbrs + e0 + 3) : 0;
        }

        int pidx = p0 + ptl;
        float2 pp = __ldg(&pos[(pidx < n_pts) ? pidx : 0]);
        float2 q0 = __ldg(&pos[nbq.x]);
        float2 q1 = __ldg(&pos[nbq.y]);
        float2 q2 = __ldg(&pos[nbq.z]);
        float2 q3 = __ldg(&pos[nbq.w]);

        float2* dst = &ssw[ptl * SSW_STRIDE + g * 4];
        float sr, sa;
        edge_geom(q0.x - pp.x, q0.y - pp.y, sr, sa); dst[0] = make_float2(sr, sa);
        edge_geom(q1.x - pp.x, q1.y - pp.y, sr, sa); dst[1] = make_float2(sr, sa);
        edge_geom(q2.x - pp.x, q2.y - pp.y, sr, sa); dst[2] = make_float2(sr, sa);
        edge_geom(q3.x - pp.x, q3.y - pp.y, sr, sa); dst[3] = make_float2(sr, sa);
    }
    __syncthreads();

    // ---- Phase 2 ----
    int point = p0 + (tid >> 2);
    int t     = tid & 3;

    bool valid = (point < n_pts);
    int pclamp = valid ? point : 0;

    int beg = valid ? __ldg(rsp + pclamp)     : 0;
    int end = valid ? __ldg(rsp + pclamp + 1) : 0;
    int cnt = end - beg;

    bool fast = valid && (cnt == 16) && (beg == (point << 4));

    const float2* f2 = (const float2*)feat;

    u64 Zp[16];
    #pragma unroll
    for (int k = 0; k < 16; ++k) Zp[k] = 0ull;

    if (fast) {
        int lpt = point - p0;
        const float2* swp = &ssw[lpt * SSW_STRIDE];
        const int4* nb4 = (const int4*)(nbrs + beg);

        #pragma unroll
        for (int g = 0; g < 4; ++g) {
            int4 nbq = __ldg(nb4 + g);      // broadcast in group, L1-hot
            float2 Fa = __ldg(&f2[(unsigned)nbq.x * 4 + t]);
            float2 Fb = __ldg(&f2[(unsigned)nbq.y * 4 + t]);
            float2 Fc = __ldg(&f2[(unsigned)nbq.z * 4 + t]);
            float2 Fd = __ldg(&f2[(unsigned)nbq.w * 4 + t]);

            float4 WA, WR;
            {
                float4 s01 = *(const float4*)(swp + g * 4);
                decode_w(s01.x, s01.y, WA, WR); accum16(WA, WR, pack2(Fa.x, Fa.y), Zp);
                decode_w(s01.z, s01.w, WA, WR); accum16(WA, WR, pack2(Fb.x, Fb.y), Zp);
            }
            {
                float4 s23 = *(const float4*)(swp + g * 4 + 2);
                decode_w(s23.x, s23.y, WA, WR); accum16(WA, WR, pack2(Fc.x, Fc.y), Zp);
                decode_w(s23.z, s23.w, WA, WR); accum16(WA, WR, pack2(Fd.x, Fd.y), Zp);
            }
        }
    } else if (valid) {
        const float2 pp = __ldg(&pos[pclamp]);
        for (int e = beg; e < end; ++e) {
            int nb = __ldg(nbrs + e);
            float2 q = __ldg(&pos[nb]);
            float sr, sa;
            edge_geom(q.x - pp.x, q.y - pp.y, sr, sa);
            float4 WA, WR;
            decode_w(sr, sa, WA, WR);
            float2 fv = __ldg(&f2[nb * 4 + t]);
            accum16(WA, WR, pack2(fv.x, fv.y), Zp);
        }
    }

    // ---- Epilogue: K via broadcast LDG.128 from L1-resident g_k ----
    float pr[8];
    #pragma unroll
    for (int i = 0; i < 8; ++i) {
        u64 a0 = 0ull, a1 = 0ull;           // two chains: halve dependency depth
        #pragma unroll
        for (int nm2 = 0; nm2 < 8; nm2 += 2) {
            ulonglong2 k0 = __ldg(&g_k[(i * 8 + nm2)     * 4 + t]);
            ulonglong2 k1 = __ldg(&g_k[(i * 8 + nm2 + 1) * 4 + t]);
            a0 = fma2(k0.x, Zp[2 * nm2],     a0);
            a0 = fma2(k0.y, Zp[2 * nm2 + 1], a0);
            a1 = fma2(k1.x, Zp[2 * nm2 + 2], a1);
            a1 = fma2(k1.y, Zp[2 * nm2 + 3], a1);
        }
        u64 acc = add2(a0, a1);
        float lo, hi;
        unpack2(acc, lo, hi);
        pr[i] = lo + hi;
    }

    #pragma unroll
    for (int i = 0; i < 8; ++i) {
        pr[i] += __shfl_xor_sync(0xffffffffu, pr[i], 1);
        pr[i] += __shfl_xor_sync(0xffffffffu, pr[i], 2);
    }

    if (valid) {
        float o0 = pr[0], o1 = pr[4];
        if (t == 1) { o0 = pr[1]; o1 = pr[5]; }
        if (t == 2) { o0 = pr[2]; o1 = pr[6]; }
        if (t == 3) { o0 = pr[3]; o1 = pr[7]; }
        out[point * 8 + t]     = o0;
        out[point * 8 + 4 + t] = o1;
    }
}

extern "C" void kernel_launch(void* const* d_in, const int* in_sizes, int n_in,
                              void* d_out, int out_size)
{
    const float* positions  = (const float*)d_in[0];
    const float* features   = (const float*)d_in[1];
    const float* kernel     = (const float*)d_in[2];
    const int*   neighbors  = (const int*)d_in[3];
    const int*   row_splits = (const int*)d_in[4];
    float*       out        = (float*)d_out;

    int n_pts   = in_sizes[0] / 2;
    int n_edges = in_sizes[3];

    repack_kernel<<<1, 256>>>(kernel);

    int blocks = (n_pts + PTS_PER_BLOCK - 1) / PTS_PER_BLOCK;
    rbf_layer_kernel<<<blocks, BLOCK_THREADS>>>(
        (const float2*)positions, features, neighbors, row_splits,
        out, n_pts, n_edges);
}

// round 13
// speedup vs baseline: 1.2281x; 1.2281x over previous
#include <cuda_runtime.h>
#include <math.h>

// rbfLayer, round 13: R10 base (best: 32.5us) + depth-1 cross-group feature
// pipeline at occupancy 7. Epilogue K stays in smem (R12 proved LDG-latency
// kills it); weights stay raw (sr,sa) in smem (R11 proved decoded-weight LDS
// traffic kills it). Phase-1 stores packed as STS.128; nbr quads read directly
// from gmem (broadcast LDG, L1-hot); epilogue accumulators split in 2 chains.

#define PTS_PER_BLOCK 32
#define BLOCK_THREADS 128
#define SSW_STRIDE 18          // float2 per point row (16 + 2 pad)

typedef unsigned long long u64;

__device__ __forceinline__ u64 pack2(float lo, float hi) {
    u64 r;
    asm("mov.b64 %0, {%1,%2};" : "=l"(r)
        : "r"(__float_as_int(lo)), "r"(__float_as_int(hi)));
    return r;
}
__device__ __forceinline__ void unpack2(u64 v, float& lo, float& hi) {
    int a, b;
    asm("mov.b64 {%0,%1}, %2;" : "=r"(a), "=r"(b) : "l"(v));
    lo = __int_as_float(a); hi = __int_as_float(b);
}
__device__ __forceinline__ u64 fma2(u64 a, u64 b, u64 c) {
    u64 d;
    asm("fma.rn.f32x2 %0, %1, %2, %3;" : "=l"(d) : "l"(a), "l"(b), "l"(c));
    return d;
}
__device__ __forceinline__ u64 mul2(u64 a, u64 b) {
    u64 d;
    asm("mul.rn.f32x2 %0, %1, %2;" : "=l"(d) : "l"(a), "l"(b));
    return d;
}
__device__ __forceinline__ u64 add2(u64 a, u64 b) {
    u64 d;
    asm("add.rn.f32x2 %0, %1, %2;" : "=l"(d) : "l"(a), "l"(b));
    return d;
}

__device__ __forceinline__ void edge_geom(float dx, float dy,
                                          float& sr, float& sa) {
    float d2 = fmaxf(fmaf(dx, dx, dy * dy), 1e-24f);
    float rinv = rsqrtf(d2);
    sr = d2 * rinv * 1.5f;

    float ax = fabsf(dx), ay = fabsf(dy);
    float mn = fminf(ax, ay);
    float mx = fmaxf(fmaxf(ax, ay), 1e-30f);
    float tq = __fdividef(mn, mx);
    float t2 = tq * tq;
    float pl = -0.0117212f;
    pl = fmaf(pl, t2, 0.05265332f);
    pl = fmaf(pl, t2, -0.11643287f);
    pl = fmaf(pl, t2, 0.19354346f);
    pl = fmaf(pl, t2, -0.33262347f);
    pl = fmaf(pl, t2, 0.99997726f);
    float ang = pl * tq;
    if (ay > ax) ang = 1.5707963267948966f - ang;
    if (dx < 0.0f) ang = 3.141592653589793f - ang;
    float th = ang * 0.3183098861837907f;
    th = (dy < 0.0f) ? -th : th;
    sa = fmaf(th, 2.0f, 2.0f);
}

__device__ __forceinline__ void decode_w(float sr, float sa,
                                         float4& WA, float4& WR) {
    int   kr = (int)sr;
    float fr = sr - (float)kr;
    int   ka = (int)sa;
    float fa = sa - (float)ka;
    int   k0 = ka & 3;
    int   k1 = (ka + 1) & 3;

    WA.x = (k0 == 0) ? (1.0f - fa) : ((k1 == 0) ? fa : 0.0f);
    WA.y = (k0 == 1) ? (1.0f - fa) : ((k1 == 1) ? fa : 0.0f);
    WA.z = (k0 == 2) ? (1.0f - fa) : ((k1 == 2) ? fa : 0.0f);
    WA.w = (k0 == 3) ? (1.0f - fa) : ((k1 == 3) ? fa : 0.0f);

    WR.x = (kr == 0) ? (1.0f - fr) : 0.0f;
    WR.y = (kr == 1) ? (1.0f - fr) : ((kr == 0) ? fr : 0.0f);
    WR.z = (kr == 2) ? (1.0f - fr) : ((kr == 1) ? fr : 0.0f);
    WR.w = (kr == 2) ? fr : 0.0f;
}

__device__ __forceinline__ void accum16(const float4& WA, const float4& WR,
                                        u64 fv2, u64 Zp[16]) {
    u64 t0 = mul2(pack2(WA.x, WA.x), fv2);
    u64 t1 = mul2(pack2(WA.y, WA.y), fv2);
    u64 t2 = mul2(pack2(WA.z, WA.z), fv2);
    u64 t3 = mul2(pack2(WA.w, WA.w), fv2);
    u64 r0 = pack2(WR.x, WR.x);
    u64 r1 = pack2(WR.y, WR.y);
    u64 r2 = pack2(WR.z, WR.z);
    u64 r3 = pack2(WR.w, WR.w);

    Zp[0]  = fma2(r0, t0, Zp[0]);   Zp[1]  = fma2(r0, t1, Zp[1]);
    Zp[2]  = fma2(r0, t2, Zp[2]);   Zp[3]  = fma2(r0, t3, Zp[3]);
    Zp[4]  = fma2(r1, t0, Zp[4]);   Zp[5]  = fma2(r1, t1, Zp[5]);
    Zp[6]  = fma2(r1, t2, Zp[6]);   Zp[7]  = fma2(r1, t3, Zp[7]);
    Zp[8]  = fma2(r2, t0, Zp[8]);   Zp[9]  = fma2(r2, t1, Zp[9]);
    Zp[10] = fma2(r2, t2, Zp[10]);  Zp[11] = fma2(r2, t3, Zp[11]);
    Zp[12] = fma2(r3, t0, Zp[12]);  Zp[13] = fma2(r3, t1, Zp[13]);
    Zp[14] = fma2(r3, t2, Zp[14]);  Zp[15] = fma2(r3, t3, Zp[15]);
}

__global__ __launch_bounds__(BLOCK_THREADS, 7)
void rbf_layer_kernel(const float2* __restrict__ pos,
                      const float*  __restrict__ feat,
                      const float*  __restrict__ kern,
                      const int*    __restrict__ nbrs,
                      const int*    __restrict__ rsp,
                      float*        __restrict__ out,
                      int n_pts, int n_edges)
{
    __shared__ ulonglong2 sk2[8 * 8 * 4];               // 4 KB epilogue K
    __shared__ float2 ssw[PTS_PER_BLOCK * SSW_STRIDE];  // 4.6 KB (sr,sa)

    int tid = threadIdx.x;

    for (int idx = tid; idx < 256; idx += BLOCK_THREADS) {
        int tt  = idx & 3;
        int nm2 = (idx >> 2) & 7;
        int i   = idx >> 5;
        int n0 = 2 * nm2, n1 = 2 * nm2 + 1;
        ulonglong2 v;
        v.x = pack2(kern[(i * 8 + 2 * tt)     * 16 + n0],
                    kern[(i * 8 + 2 * tt + 1) * 16 + n0]);
        v.y = pack2(kern[(i * 8 + 2 * tt)     * 16 + n1],
                    kern[(i * 8 + 2 * tt + 1) * 16 + n1]);
        sk2[idx] = v;
    }

    int p0 = blockIdx.x * PTS_PER_BLOCK;

    // ---- Phase 1: geometry -> smem (uniform-row assumption; phase 2
    //      verifies beg==16*point && cnt==16 before using it) ----
    {
        int ptl = tid >> 2;                 // local point 0..31
        int g   = tid & 3;                  // edge quad 0..3
        int e0  = (p0 + ptl) * 16 + g * 4;
        int4 nbq;
        if (e0 + 3 < n_edges) {
            nbq = __ldg((const int4*)(nbrs + e0));
        } else {
            nbq.x = (e0 + 0 < n_edges) ? __ldg(nbrs + e0 + 0) : 0;
            nbq.y = (e0 + 1 < n_edges) ? __ldg(nbrs + e0 + 1) : 0;
            nbq.z = (e0 + 2 < n_edges) ? __ldg(nbrs + e0 + 2) : 0;
            nbq.w = (e0 + 3 < n_edges) ? __ldg(nbrs + e0 + 3) : 0;
        }

        int pidx = p0 + ptl;
        float2 pp = __ldg(&pos[(pidx < n_pts) ? pidx : 0]);
        float2 q0 = __ldg(&pos[nbq.x]);
        float2 q1 = __ldg(&pos[nbq.y]);
        float2 q2 = __ldg(&pos[nbq.z]);
        float2 q3 = __ldg(&pos[nbq.w]);

        float4* dst = (float4*)&ssw[ptl * SSW_STRIDE + g * 4];
        float sr0, sa0, sr1, sa1;
        edge_geom(q0.x - pp.x, q0.y - pp.y, sr0, sa0);
        edge_geom(q1.x - pp.x, q1.y - pp.y, sr1, sa1);
        dst[0] = make_float4(sr0, sa0, sr1, sa1);       // STS.128
        edge_geom(q2.x - pp.x, q2.y - pp.y, sr0, sa0);
        edge_geom(q3.x - pp.x, q3.y - pp.y, sr1, sa1);
        dst[1] = make_float4(sr0, sa0, sr1, sa1);       // STS.128
    }
    __syncthreads();

    // ---- Phase 2 ----
    int point = p0 + (tid >> 2);
    int t     = tid & 3;

    bool valid = (point < n_pts);
    int pclamp = valid ? point : 0;

    int beg = valid ? __ldg(rsp + pclamp)     : 0;
    int end = valid ? __ldg(rsp + pclamp + 1) : 0;
    int cnt = end - beg;

    bool fast = valid && (cnt == 16) && (beg == (point << 4));

    const float2* f2 = (const float2*)feat;

    u64 Zp[16];
    #pragma unroll
    for (int k = 0; k < 16; ++k) Zp[k] = 0ull;

    if (fast) {
        int lpt = point - p0;
        const float2* swp = &ssw[lpt * SSW_STRIDE];
        const int4* nb4 = (const int4*)(nbrs + beg);

        // prologue: group 0 gathers in flight
        int4 nbq = __ldg(nb4 + 0);
        float2 Fa = __ldg(&f2[(unsigned)nbq.x * 4 + t]);
        float2 Fb = __ldg(&f2[(unsigned)nbq.y * 4 + t]);
        float2 Fc = __ldg(&f2[(unsigned)nbq.z * 4 + t]);
        float2 Fd = __ldg(&f2[(unsigned)nbq.w * 4 + t]);

        #pragma unroll
        for (int g = 0; g < 4; ++g) {
            float2 Na, Nb, Nc, Nd;
            if (g < 3) {                      // prefetch group g+1
                int4 nq = __ldg(nb4 + g + 1);
                Na = __ldg(&f2[(unsigned)nq.x * 4 + t]);
                Nb = __ldg(&f2[(unsigned)nq.y * 4 + t]);
                Nc = __ldg(&f2[(unsigned)nq.z * 4 + t]);
                Nd = __ldg(&f2[(unsigned)nq.w * 4 + t]);
            }
            float4 WA, WR;
            {
                float4 s01 = *(const float4*)(swp + g * 4);
                decode_w(s01.x, s01.y, WA, WR); accum16(WA, WR, pack2(Fa.x, Fa.y), Zp);
                decode_w(s01.z, s01.w, WA, WR); accum16(WA, WR, pack2(Fb.x, Fb.y), Zp);
            }
            {
                float4 s23 = *(const float4*)(swp + g * 4 + 2);
                decode_w(s23.x, s23.y, WA, WR); accum16(WA, WR, pack2(Fc.x, Fc.y), Zp);
                decode_w(s23.z, s23.w, WA, WR); accum16(WA, WR, pack2(Fd.x, Fd.y), Zp);
            }
            Fa = Na; Fb = Nb; Fc = Nc; Fd = Nd;
        }
    } else if (valid) {
        const float2 pp = __ldg(&pos[pclamp]);
        for (int e = beg; e < end; ++e) {
            int nb = __ldg(nbrs + e);
            float2 q = __ldg(&pos[nb]);
            float sr, sa;
            edge_geom(q.x - pp.x, q.y - pp.y, sr, sa);
            float4 WA, WR;
            decode_w(sr, sa, WA, WR);
            float2 fv = __ldg(&f2[nb * 4 + t]);
            accum16(WA, WR, pack2(fv.x, fv.y), Zp);
        }
    }

    // ---- Epilogue: smem K, two dependency chains per output ----
    float pr[8];
    #pragma unroll
    for (int i = 0; i < 8; ++i) {
        u64 a0 = 0ull, a1 = 0ull;
        #pragma unroll
        for (int nm2 = 0; nm2 < 8; nm2 += 2) {
            ulonglong2 k0 = sk2[(i * 8 + nm2)     * 4 + t];
            ulonglong2 k1 = sk2[(i * 8 + nm2 + 1) * 4 + t];
            a0 = fma2(k0.x, Zp[2 * nm2],     a0);
            a0 = fma2(k0.y, Zp[2 * nm2 + 1], a0);
            a1 = fma2(k1.x, Zp[2 * nm2 + 2], a1);
            a1 = fma2(k1.y, Zp[2 * nm2 + 3], a1);
        }
        u64 acc = add2(a0, a1);
        float lo, hi;
        unpack2(acc, lo, hi);
        pr[i] = lo + hi;
    }

    #pragma unroll
    for (int i = 0; i < 8; ++i) {
        pr[i] += __shfl_xor_sync(0xffffffffu, pr[i], 1);
        pr[i] += __shfl_xor_sync(0xffffffffu, pr[i], 2);
    }

    if (valid) {
        float o0 = pr[0], o1 = pr[4];
        if (t == 1) { o0 = pr[1]; o1 = pr[5]; }
        if (t == 2) { o0 = pr[2]; o1 = pr[6]; }
        if (t == 3) { o0 = pr[3]; o1 = pr[7]; }
        out[point * 8 + t]     = o0;
        out[point * 8 + 4 + t] = o1;
    }
}

extern "C" void kernel_launch(void* const* d_in, const int* in_sizes, int n_in,
                              void* d_out, int out_size)
{
    const float* positions  = (const float*)d_in[0];
    const float* features   = (const float*)d_in[1];
    const float* kernel     = (const float*)d_in[2];
    const int*   neighbors  = (const int*)d_in[3];
    const int*   row_splits = (const int*)d_in[4];
    float*       out        = (float*)d_out;

    int n_pts   = in_sizes[0] / 2;
    int n_edges = in_sizes[3];

    int blocks = (n_pts + PTS_PER_BLOCK - 1) / PTS_PER_BLOCK;
    rbf_layer_kernel<<<blocks, BLOCK_THREADS>>>(
        (const float2*)positions, features, kernel, neighbors, row_splits,
        out, n_pts, n_edges);
}

// round 14
// speedup vs baseline: 1.3242x; 1.0783x over previous
#include <cuda_runtime.h>
#include <math.h>

// rbfLayer, round 14: R10 shell (proven optimum) + branch-free float-only
// hat decode (no F2I/I2F cvts, no ISETP chains -> all lat-4 fma-pipe ops),
// 256-thread blocks (setup amortization), STS.128 phase-1 packing,
// 2-chain epilogue. No software prefetch (falsified twice: R9-pipe, R13).
//   radial : wr_n = max(0, 1 - |sr - n|)                (sr in [0,3))
//   angular: wa_m = max(0, max(1 - |sa-m|, |sa-m| - 3)) (period-4 cyclic)

#define PTS_PER_BLOCK 64
#define BLOCK_THREADS 256
#define SSW_STRIDE 18          // float2 per point row (16 + 2 pad)

typedef unsigned long long u64;

__device__ __forceinline__ u64 pack2(float lo, float hi) {
    u64 r;
    asm("mov.b64 %0, {%1,%2};" : "=l"(r)
        : "r"(__float_as_int(lo)), "r"(__float_as_int(hi)));
    return r;
}
__device__ __forceinline__ void unpack2(u64 v, float& lo, float& hi) {
    int a, b;
    asm("mov.b64 {%0,%1}, %2;" : "=r"(a), "=r"(b) : "l"(v));
    lo = __int_as_float(a); hi = __int_as_float(b);
}
__device__ __forceinline__ u64 fma2(u64 a, u64 b, u64 c) {
    u64 d;
    asm("fma.rn.f32x2 %0, %1, %2, %3;" : "=l"(d) : "l"(a), "l"(b), "l"(c));
    return d;
}
__device__ __forceinline__ u64 mul2(u64 a, u64 b) {
    u64 d;
    asm("mul.rn.f32x2 %0, %1, %2;" : "=l"(d) : "l"(a), "l"(b));
    return d;
}
__device__ __forceinline__ u64 add2(u64 a, u64 b) {
    u64 d;
    asm("add.rn.f32x2 %0, %1, %2;" : "=l"(d) : "l"(a), "l"(b));
    return d;
}

__device__ __forceinline__ void edge_geom(float dx, float dy,
                                          float& sr, float& sa) {
    float d2 = fmaxf(fmaf(dx, dx, dy * dy), 1e-24f);
    float rinv = rsqrtf(d2);
    sr = d2 * rinv * 1.5f;

    float ax = fabsf(dx), ay = fabsf(dy);
    float mn = fminf(ax, ay);
    float mx = fmaxf(fmaxf(ax, ay), 1e-30f);
    float tq = __fdividef(mn, mx);
    float t2 = tq * tq;
    float pl = -0.0117212f;
    pl = fmaf(pl, t2, 0.05265332f);
    pl = fmaf(pl, t2, -0.11643287f);
    pl = fmaf(pl, t2, 0.19354346f);
    pl = fmaf(pl, t2, -0.33262347f);
    pl = fmaf(pl, t2, 0.99997726f);
    float ang = pl * tq;
    if (ay > ax) ang = 1.5707963267948966f - ang;
    if (dx < 0.0f) ang = 3.141592653589793f - ang;
    float th = ang * 0.3183098861837907f;
    th = (dy < 0.0f) ? -th : th;
    sa = fmaf(th, 2.0f, 2.0f);
}

// Branch-free PoU hat decode: only FADD/FABS/FMNMX, all lat-4.
__device__ __forceinline__ void decode_w(float sr, float sa,
                                         float4& WA, float4& WR) {
    float a0 = fabsf(sa);
    float a1 = fabsf(sa - 1.0f);
    float a2 = fabsf(sa - 2.0f);
    float a3 = fabsf(sa - 3.0f);
    WA.x = fmaxf(0.0f, fmaxf(1.0f - a0, a0 - 3.0f));
    WA.y = fmaxf(0.0f, fmaxf(1.0f - a1, a1 - 3.0f));
    WA.z = fmaxf(0.0f, fmaxf(1.0f - a2, a2 - 3.0f));
    WA.w = fmaxf(0.0f, fmaxf(1.0f - a3, a3 - 3.0f));

    WR.x = fmaxf(0.0f, 1.0f - fabsf(sr));
    WR.y = fmaxf(0.0f, 1.0f - fabsf(sr - 1.0f));
    WR.z = fmaxf(0.0f, 1.0f - fabsf(sr - 2.0f));
    WR.w = fmaxf(0.0f, 1.0f - fabsf(sr - 3.0f));
}

__device__ __forceinline__ void accum16(const float4& WA, const float4& WR,
                                        u64 fv2, u64 Zp[16]) {
    u64 t0 = mul2(pack2(WA.x, WA.x), fv2);
    u64 t1 = mul2(pack2(WA.y, WA.y), fv2);
    u64 t2 = mul2(pack2(WA.z, WA.z), fv2);
    u64 t3 = mul2(pack2(WA.w, WA.w), fv2);
    u64 r0 = pack2(WR.x, WR.x);
    u64 r1 = pack2(WR.y, WR.y);
    u64 r2 = pack2(WR.z, WR.z);
    u64 r3 = pack2(WR.w, WR.w);

    Zp[0]  = fma2(r0, t0, Zp[0]);   Zp[1]  = fma2(r0, t1, Zp[1]);
    Zp[2]  = fma2(r0, t2, Zp[2]);   Zp[3]  = fma2(r0, t3, Zp[3]);
    Zp[4]  = fma2(r1, t0, Zp[4]);   Zp[5]  = fma2(r1, t1, Zp[5]);
    Zp[6]  = fma2(r1, t2, Zp[6]);   Zp[7]  = fma2(r1, t3, Zp[7]);
    Zp[8]  = fma2(r2, t0, Zp[8]);   Zp[9]  = fma2(r2, t1, Zp[9]);
    Zp[10] = fma2(r2, t2, Zp[10]);  Zp[11] = fma2(r2, t3, Zp[11]);
    Zp[12] = fma2(r3, t0, Zp[12]);  Zp[13] = fma2(r3, t1, Zp[13]);
    Zp[14] = fma2(r3, t2, Zp[14]);  Zp[15] = fma2(r3, t3, Zp[15]);
}

__global__ __launch_bounds__(BLOCK_THREADS, 4)
void rbf_layer_kernel(const float2* __restrict__ pos,
                      const float*  __restrict__ feat,
                      const float*  __restrict__ kern,
                      const int*    __restrict__ nbrs,
                      const int*    __restrict__ rsp,
                      float*        __restrict__ out,
                      int n_pts, int n_edges)
{
    __shared__ ulonglong2 sk2[8 * 8 * 4];               // 4 KB epilogue K
    __shared__ float2 ssw[PTS_PER_BLOCK * SSW_STRIDE];  // 9.2 KB (sr,sa)

    int tid = threadIdx.x;

    // one entry per thread (256 == table size)
    {
        int idx = tid;
        int tt  = idx & 3;
        int nm2 = (idx >> 2) & 7;
        int i   = idx >> 5;
        int n0 = 2 * nm2, n1 = 2 * nm2 + 1;
        ulonglong2 v;
        v.x = pack2(kern[(i * 8 + 2 * tt)     * 16 + n0],
                    kern[(i * 8 + 2 * tt + 1) * 16 + n0]);
        v.y = pack2(kern[(i * 8 + 2 * tt)     * 16 + n1],
                    kern[(i * 8 + 2 * tt + 1) * 16 + n1]);
        sk2[idx] = v;
    }

    int p0 = blockIdx.x * PTS_PER_BLOCK;

    // ---- Phase 1: geometry -> smem (uniform-row assumption; phase 2
    //      verifies beg==16*point && cnt==16 before using it) ----
    {
        int ptl = tid >> 2;                 // local point 0..63
        int g   = tid & 3;                  // edge quad 0..3
        int e0  = (p0 + ptl) * 16 + g * 4;
        int4 nbq;
        if (e0 + 3 < n_edges) {
            nbq = __ldg((const int4*)(nbrs + e0));
        } else {
            nbq.x = (e0 + 0 < n_edges) ? __ldg(nbrs + e0 + 0) : 0;
            nbq.y = (e0 + 1 < n_edges) ? __ldg(nbrs + e0 + 1) : 0;
            nbq.z = (e0 + 2 < n_edges) ? __ldg(nbrs + e0 + 2) : 0;
            nbq.w = (e0 + 3 < n_edges) ? __ldg(nbrs + e0 + 3) : 0;
        }

        int pidx = p0 + ptl;
        float2 pp = __ldg(&pos[(pidx < n_pts) ? pidx : 0]);
        float2 q0 = __ldg(&pos[nbq.x]);
        float2 q1 = __ldg(&pos[nbq.y]);
        float2 q2 = __ldg(&pos[nbq.z]);
        float2 q3 = __ldg(&pos[nbq.w]);

        float4* dst = (float4*)&ssw[ptl * SSW_STRIDE + g * 4];
        float sr0, sa0, sr1, sa1;
        edge_geom(q0.x - pp.x, q0.y - pp.y, sr0, sa0);
        edge_geom(q1.x - pp.x, q1.y - pp.y, sr1, sa1);
        dst[0] = make_float4(sr0, sa0, sr1, sa1);       // STS.128
        edge_geom(q2.x - pp.x, q2.y - pp.y, sr0, sa0);
        edge_geom(q3.x - pp.x, q3.y - pp.y, sr1, sa1);
        dst[1] = make_float4(sr0, sa0, sr1, sa1);       // STS.128
    }
    __syncthreads();

    // ---- Phase 2 ----
    int point = p0 + (tid >> 2);
    int t     = tid & 3;

    bool valid = (point < n_pts);
    int pclamp = valid ? point : 0;

    int beg = valid ? __ldg(rsp + pclamp)     : 0;
    int end = valid ? __ldg(rsp + pclamp + 1) : 0;
    int cnt = end - beg;

    bool fast = valid && (cnt == 16) && (beg == (point << 4));

    const float2* f2 = (const float2*)feat;

    u64 Zp[16];
    #pragma unroll
    for (int k = 0; k < 16; ++k) Zp[k] = 0ull;

    if (fast) {
        int lpt = point - p0;
        const float2* swp = &ssw[lpt * SSW_STRIDE];
        const int4* nb4 = (const int4*)(nbrs + beg);

        #pragma unroll
        for (int g = 0; g < 4; ++g) {
            int4 nbq = __ldg(nb4 + g);      // broadcast, L1-hot from phase 1
            float2 Fa = __ldg(&f2[(unsigned)nbq.x * 4 + t]);
            float2 Fb = __ldg(&f2[(unsigned)nbq.y * 4 + t]);
            float2 Fc = __ldg(&f2[(unsigned)nbq.z * 4 + t]);
            float2 Fd = __ldg(&f2[(unsigned)nbq.w * 4 + t]);

            float4 WA, WR;
            {
                float4 s01 = *(const float4*)(swp + g * 4);
                decode_w(s01.x, s01.y, WA, WR); accum16(WA, WR, pack2(Fa.x, Fa.y), Zp);
                decode_w(s01.z, s01.w, WA, WR); accum16(WA, WR, pack2(Fb.x, Fb.y), Zp);
            }
            {
                float4 s23 = *(const float4*)(swp + g * 4 + 2);
                decode_w(s23.x, s23.y, WA, WR); accum16(WA, WR, pack2(Fc.x, Fc.y), Zp);
                decode_w(s23.z, s23.w, WA, WR); accum16(WA, WR, pack2(Fd.x, Fd.y), Zp);
            }
        }
    } else if (valid) {
        const float2 pp = __ldg(&pos[pclamp]);
        for (int e = beg; e < end; ++e) {
            int nb = __ldg(nbrs + e);
            float2 q = __ldg(&pos[nb]);
            float sr, sa;
            edge_geom(q.x - pp.x, q.y - pp.y, sr, sa);
            float4 WA, WR;
            decode_w(sr, sa, WA, WR);
            float2 fv = __ldg(&f2[nb * 4 + t]);
            accum16(WA, WR, pack2(fv.x, fv.y), Zp);
        }
    }

    // ---- Epilogue: smem K, two dependency chains per output ----
    float pr[8];
    #pragma unroll
    for (int i = 0; i < 8; ++i) {
        u64 a0 = 0ull, a1 = 0ull;
        #pragma unroll
        for (int nm2 = 0; nm2 < 8; nm2 += 2) {
            ulonglong2 k0 = sk2[(i * 8 + nm2)     * 4 + t];
            ulonglong2 k1 = sk2[(i * 8 + nm2 + 1) * 4 + t];
            a0 = fma2(k0.x, Zp[2 * nm2],     a0);
            a0 = fma2(k0.y, Zp[2 * nm2 + 1], a0);
            a1 = fma2(k1.x, Zp[2 * nm2 + 2], a1);
            a1 = fma2(k1.y, Zp[2 * nm2 + 3], a1);
        }
        u64 acc = add2(a0, a1);
        float lo, hi;
        unpack2(acc, lo, hi);
        pr[i] = lo + hi;
    }

    #pragma unroll
    for (int i = 0; i < 8; ++i) {
        pr[i] += __shfl_xor_sync(0xffffffffu, pr[i], 1);
        pr[i] += __shfl_xor_sync(0xffffffffu, pr[i], 2);
    }

    if (valid) {
        float o0 = pr[0], o1 = pr[4];
        if (t == 1) { o0 = pr[1]; o1 = pr[5]; }
        if (t == 2) { o0 = pr[2]; o1 = pr[6]; }
        if (t == 3) { o0 = pr[3]; o1 = pr[7]; }
        out[point * 8 + t]     = o0;
        out[point * 8 + 4 + t] = o1;
    }
}

extern "C" void kernel_launch(void* const* d_in, const int* in_sizes, int n_in,
                              void* d_out, int out_size)
{
    const float* positions  = (const float*)d_in[0];
    const float* features   = (const float*)d_in[1];
    const float* kernel     = (const float*)d_in[2];
    const int*   neighbors  = (const int*)d_in[3];
    const int*   row_splits = (const int*)d_in[4];
    float*       out        = (float*)d_out;

    int n_pts   = in_sizes[0] / 2;
    int n_edges = in_sizes[3];

    int blocks = (n_pts + PTS_PER_BLOCK - 1) / PTS_PER_BLOCK;
    rbf_layer_kernel<<<blocks, BLOCK_THREADS>>>(
        (const float2*)positions, features, kernel, neighbors, row_splits,
        out, n_pts, n_edges);
}